// round 3
// baseline (speedup 1.0000x reference)
#include <cuda_runtime.h>

#define S_ 8
#define U_ 32
#define V_ 32
#define C_ 32
#define SU 256   // S_*U_
#define SV 256   // S_*V_
#define CHUNK 8
#define TROWS 128
#define SPAD 36              // float2 stride per s-slice (32 + 4 pad) -> bank spread
#define ROWSTRIDE (S_*SPAD)  // 288 float2 per staged row

// Thread = (s, vpair-group of 2) computing 4 consecutive v outputs (P=2).
// Weights: 128 regs of premultiplied packed {w,w'} pairs, reloaded per segment.
// x staged in SMEM duplicated {x,x} with per-s padding so broadcast LDS.128
// is bank-conflict-free (64B unique/instr). Compute = pure LDS.128 + fma.f32x2.
__global__ __launch_bounds__(128, 3)
void idxlin_kernel(const float* __restrict__ W,     // (C, S*U*V)
                   const float* __restrict__ X,     // (Z, S*U)
                   const int*   __restrict__ counts,
                   const float* __restrict__ coef,
                   float* __restrict__ out,         // (Z, S*V)
                   int Z)
{
    __shared__ __align__(16) float2 x_sh[CHUNK * ROWSTRIDE];  // 18.4 KB
    __shared__ int segStart[C_ + 1];

    const int tid = threadIdx.x;
    if (tid == 0) {
        int acc = 0; segStart[0] = 0;
        #pragma unroll
        for (int c = 0; c < C_; ++c) { acc += counts[c]; segStart[c + 1] = acc; }
    }
    __syncthreads();

    const int vpg = tid & 7;          // which group of 4 v's
    const int s   = (tid >> 3) & 7;
    const int rg  = tid >> 6;         // row-group half of chunk
    const int ric_st = tid >> 4;      // staging row-in-chunk 0..7
    const int c16 = tid & 15;

    const int blockStart = blockIdx.x * TROWS;
    const int blockEnd   = min(blockStart + TROWS, Z);

    unsigned long long wa[U_], wb[U_];   // packed {W[u,v0],W[u,v1]}*c, {W[u,v2],W[u,v3]}*c

    int cur = blockStart;
    int seg = 0;
    while (seg < C_ - 1 && segStart[seg + 1] <= cur) seg++;

    while (cur < blockEnd) {
        const int segTop = (seg < C_ - 1) ? segStart[seg + 1] : Z;
        const int segEnd = min(segTop, blockEnd);

        if (segEnd > cur) {
            const float c0 = coef[s];
            const float4* wp = reinterpret_cast<const float4*>(
                W + (size_t)seg * (S_ * U_ * V_) + s * (U_ * V_) + vpg * 4);
            #pragma unroll
            for (int u = 0; u < U_; ++u) {
                float4 w = wp[u * (V_ / 4)];
                w.x *= c0; w.y *= c0; w.z *= c0; w.w *= c0;
                float2 lo = make_float2(w.x, w.y);
                float2 hi = make_float2(w.z, w.w);
                wa[u] = *reinterpret_cast<unsigned long long*>(&lo);
                wb[u] = *reinterpret_cast<unsigned long long*>(&hi);
            }

            for (int r0 = cur; r0 < segEnd; r0 += CHUNK) {
                const int nr = min(CHUNK, segEnd - r0);
                __syncthreads();
                // Stage nr rows, duplicated, padded layout. su = c16 + 16k gives
                // STS.64 bank stride 2 -> minimal 2-phase cost (256B unique).
                if (ric_st < nr) {
                    const float* xr = X + (size_t)(r0 + ric_st) * SU;
                    #pragma unroll
                    for (int k = 0; k < SU / 16; ++k) {
                        int su = c16 + 16 * k;
                        float v = xr[su];
                        x_sh[ric_st * ROWSTRIDE + (su >> 5) * SPAD + (su & 31)]
                            = make_float2(v, v);
                    }
                }
                __syncthreads();

                #pragma unroll
                for (int rr = 0; rr < CHUNK / 2; ++rr) {
                    const int ric = rg * (CHUNK / 2) + rr;
                    if (ric < nr) {
                        const float4* xs = reinterpret_cast<const float4*>(
                            &x_sh[ric * ROWSTRIDE + s * SPAD]);
                        unsigned long long a0 = 0ULL, a1 = 0ULL;
                        unsigned long long b0 = 0ULL, b1 = 0ULL;
                        #pragma unroll
                        for (int i = 0; i < U_ / 2; ++i) {
                            float4 q = xs[i];  // {x[2i],x[2i], x[2i+1],x[2i+1]}
                            unsigned long long xa = *reinterpret_cast<unsigned long long*>(&q.x);
                            unsigned long long xb = *reinterpret_cast<unsigned long long*>(&q.z);
                            asm("fma.rn.f32x2 %0, %1, %2, %0;" : "+l"(a0) : "l"(xa), "l"(wa[2*i]));
                            asm("fma.rn.f32x2 %0, %1, %2, %0;" : "+l"(b0) : "l"(xa), "l"(wb[2*i]));
                            asm("fma.rn.f32x2 %0, %1, %2, %0;" : "+l"(a1) : "l"(xb), "l"(wa[2*i+1]));
                            asm("fma.rn.f32x2 %0, %1, %2, %0;" : "+l"(b1) : "l"(xb), "l"(wb[2*i+1]));
                        }
                        unsigned long long ra, rb;
                        asm("add.rn.f32x2 %0, %1, %2;" : "=l"(ra) : "l"(a0), "l"(a1));
                        asm("add.rn.f32x2 %0, %1, %2;" : "=l"(rb) : "l"(b0), "l"(b1));
                        float2 fa = *reinterpret_cast<float2*>(&ra);
                        float2 fb = *reinterpret_cast<float2*>(&rb);
                        float4 res = make_float4(fa.x, fa.y, fb.x, fb.y);
                        // Warp covers 512B contiguous of the output row: coalesced.
                        *reinterpret_cast<float4*>(
                            out + (size_t)(r0 + ric) * SV + s * V_ + vpg * 4) = res;
                    }
                }
            }
        }
        cur = segEnd > cur ? segEnd : cur;
        if (cur < blockEnd) {
            seg++;
            if (seg >= C_) break;  // safety
        }
    }
}

extern "C" void kernel_launch(void* const* d_in, const int* in_sizes, int n_in,
                              void* d_out, int out_size) {
    const float* W      = (const float*)d_in[0];   // input1 (C, S*U*V)
    const float* X      = (const float*)d_in[1];   // input2 (Z, S*U)
    const int*   counts = (const int*)d_in[2];
    const float* coef   = (const float*)d_in[3];
    float* out = (float*)d_out;

    int Z = in_sizes[1] / SU;
    int grid = (Z + TROWS - 1) / TROWS;
    idxlin_kernel<<<grid, 128>>>(W, X, counts, coef, out, Z);
}